// round 2
// baseline (speedup 1.0000x reference)
#include <cuda_runtime.h>
#include <cstdint>

typedef unsigned long long u64;

#define BM 128
#define BN 128
#define BK 16
#define TM 8
#define TN 8
#define NTHREADS 256

// Scratch scalars (allowed: __device__ globals, no allocation)
__device__ double g_abs_sum;
__device__ float  g_inv_scale;

// ---------------- packed f32x2 helpers (sm_100+ PTX) ----------------
__device__ __forceinline__ u64 pk2(float a, float b) {
    u64 r; asm("mov.b64 %0, {%1, %2};" : "=l"(r) : "f"(a), "f"(b)); return r;
}
__device__ __forceinline__ void upk2(float& a, float& b, u64 v) {
    asm("mov.b64 {%0, %1}, %2;" : "=f"(a), "=f"(b) : "l"(v));
}
__device__ __forceinline__ void fma2(u64& d, u64 a, u64 b) {
    asm("fma.rn.f32x2 %0, %1, %2, %3;" : "=l"(d) : "l"(a), "l"(b), "l"(d));
}

__global__ void reset_kernel() { g_abs_sum = 0.0; }

// C[M,N] = (A*s)[M,K] @ B[N,K]^T   (both operands K-contiguous => coalesced)
// Fused: per-block sum of |C| -> atomicAdd into g_abs_sum (double).
__global__ __launch_bounds__(NTHREADS)
void gemm_kernel(const float* __restrict__ A, const float* __restrict__ B,
                 const float* __restrict__ inS, const float* __restrict__ wS,
                 float* __restrict__ C, int M, int N, int K)
{
    __shared__ __align__(16) float As[BK][BM + 4];
    __shared__ __align__(16) float Bs[BK][BN + 4];
    __shared__ float red[NTHREADS / 32];

    const int tid = threadIdx.x;
    const int tx = tid & 15;        // 0..15 -> n sub-tile
    const int ty = tid >> 4;        // 0..15 -> m sub-tile
    const int m0 = blockIdx.y * BM;
    const int n0 = blockIdx.x * BN;
    const float s = inS[0] * wS[0];

    // global-load mapping: 4 float4 per 16-wide K row, 64 rows per pass, 2 passes
    const int lrow = tid >> 2;           // 0..63
    const int lk   = (tid & 3) << 2;     // 0,4,8,12

    u64 acc[TM][TN / 2];
    #pragma unroll
    for (int i = 0; i < TM; i++)
        #pragma unroll
        for (int j = 0; j < TN / 2; j++) acc[i][j] = 0ull;

    const float* Aptr = A + (size_t)(m0 + lrow) * K + lk;
    const float* Bptr = B + (size_t)(n0 + lrow) * K + lk;

    // prefetch tile 0 into registers
    float4 ra[2], rb[2];
    #pragma unroll
    for (int it = 0; it < 2; it++) {
        ra[it] = *(const float4*)(Aptr + (size_t)it * 64 * K);
        rb[it] = *(const float4*)(Bptr + (size_t)it * 64 * K);
    }

    const int ktiles = K / BK;
    for (int kt = 0; kt < ktiles; kt++) {
        // commit prefetched regs to smem (A pre-scaled so products match dequantized ref)
        #pragma unroll
        for (int it = 0; it < 2; it++) {
            int row = lrow + it * 64;
            As[lk + 0][row] = ra[it].x * s; As[lk + 1][row] = ra[it].y * s;
            As[lk + 2][row] = ra[it].z * s; As[lk + 3][row] = ra[it].w * s;
            Bs[lk + 0][row] = rb[it].x;     Bs[lk + 1][row] = rb[it].y;
            Bs[lk + 2][row] = rb[it].z;     Bs[lk + 3][row] = rb[it].w;
        }
        __syncthreads();

        // prefetch next tile (overlaps with compute below)
        if (kt + 1 < ktiles) {
            const float* An = Aptr + (size_t)(kt + 1) * BK;
            const float* Bn = Bptr + (size_t)(kt + 1) * BK;
            #pragma unroll
            for (int it = 0; it < 2; it++) {
                ra[it] = *(const float4*)(An + (size_t)it * 64 * K);
                rb[it] = *(const float4*)(Bn + (size_t)it * 64 * K);
            }
        }

        #pragma unroll
        for (int k = 0; k < BK; k++) {
            float a[TM];
            *(float4*)&a[0] = *(const float4*)&As[k][ty * TM];
            *(float4*)&a[4] = *(const float4*)&As[k][ty * TM + 4];
            u64 b2[TN / 2];
            ulonglong2 bb0 = *(const ulonglong2*)&Bs[k][tx * TN];
            ulonglong2 bb1 = *(const ulonglong2*)&Bs[k][tx * TN + 4];
            b2[0] = bb0.x; b2[1] = bb0.y; b2[2] = bb1.x; b2[3] = bb1.y;
            #pragma unroll
            for (int i = 0; i < TM; i++) {
                u64 a2 = pk2(a[i], a[i]);
                #pragma unroll
                for (int j = 0; j < TN / 2; j++) fma2(acc[i][j], a2, b2[j]);
            }
        }
        __syncthreads();
    }

    // epilogue: write raw fp32 GEMM result, accumulate sum(|v|)
    float asum = 0.f;
    #pragma unroll
    for (int i = 0; i < TM; i++) {
        float v[TN];
        #pragma unroll
        for (int j = 0; j < TN / 2; j++) upk2(v[2 * j], v[2 * j + 1], acc[i][j]);
        float4* crow = (float4*)(C + (size_t)(m0 + ty * TM + i) * N + n0 + tx * TN);
        crow[0] = make_float4(v[0], v[1], v[2], v[3]);
        crow[1] = make_float4(v[4], v[5], v[6], v[7]);
        #pragma unroll
        for (int j = 0; j < TN; j++) asum += fabsf(v[j]);
    }

    // block reduction -> double atomic
    #pragma unroll
    for (int off = 16; off > 0; off >>= 1)
        asum += __shfl_down_sync(0xffffffffu, asum, off);
    const int lane = tid & 31, wid = tid >> 5;
    if (lane == 0) red[wid] = asum;
    __syncthreads();
    if (wid == 0) {
        float v = (lane < NTHREADS / 32) ? red[lane] : 0.f;
        #pragma unroll
        for (int off = 4; off > 0; off >>= 1)
            v += __shfl_down_sync(0xffffffffu, v, off);
        if (lane == 0) atomicAdd(&g_abs_sum, (double)v);
    }
}

__global__ void finalize_kernel(float* __restrict__ scale_slot, size_t mn) {
    double mean = g_abs_sum / (double)mn;
    float scale = (float)mean;
    if (scale < 1e-5f) scale = 1e-5f;
    *scale_slot = scale;
    g_inv_scale = (float)(1.0 / (double)scale);
}

__global__ void quantize_kernel(float4* __restrict__ C, int n4) {
    int i = blockIdx.x * blockDim.x + threadIdx.x;
    if (i >= n4) return;
    const float inv = g_inv_scale;
    float4 v = C[i];
    v.x = fminf(fmaxf(rintf(v.x * inv), -1.f), 1.f);
    v.y = fminf(fmaxf(rintf(v.y * inv), -1.f), 1.f);
    v.z = fminf(fmaxf(rintf(v.z * inv), -1.f), 1.f);
    v.w = fminf(fmaxf(rintf(v.w * inv), -1.f), 1.f);
    C[i] = v;
}

extern "C" void kernel_launch(void* const* d_in, const int* in_sizes, int n_in,
                              void* d_out, int out_size)
{
    const float* x   = (const float*)d_in[0];   // [B,S,IN] fp32
    const float* inS = (const float*)d_in[1];   // scalar
    const float* qw  = (const float*)d_in[2];   // [OUT,IN] fp32 (ternary)
    const float* wS  = (const float*)d_in[3];   // scalar
    float* out = (float*)d_out;                 // [B*S*OUT] q_out, then [1] scale

    const int K = 2048;                         // IN
    const int N = 2048;                         // OUT
    const int M = in_sizes[0] / K;              // B*S = 16384
    const size_t mn = (size_t)M * (size_t)N;

    reset_kernel<<<1, 1>>>();

    dim3 grid(N / BN, M / BM);
    gemm_kernel<<<grid, NTHREADS>>>(x, qw, inS, wS, out, M, N, K);

    finalize_kernel<<<1, 1>>>(out + mn, mn);

    const int n4 = (int)(mn / 4);
    quantize_kernel<<<(n4 + 255) / 256, 256>>>((float4*)out, n4);
}

// round 6
// speedup vs baseline: 2.7348x; 2.7348x over previous
#include <cuda_runtime.h>
#include <cuda_bf16.h>
#include <cstdint>

#define MSZ 16384
#define NSZ 2048
#define KSZ 2048
#define BM 128
#define BN 128
#define BK 64
#define KTILES (KSZ / BK)                 // 32
#define THREADS 256
#define PLANE_BYTES (BM * BK * 2)         // 16384
#define STAGE_BYTES (4 * PLANE_BYTES)     // 65536: 3 A planes + B
#define SMEM_BYTES (2 * STAGE_BYTES)      // 131072

// -------- scratch (device globals: the allowed scratch mechanism) --------
__device__ __align__(16) __nv_bfloat16 g_Ah[(size_t)MSZ * KSZ];
__device__ __align__(16) __nv_bfloat16 g_Am[(size_t)MSZ * KSZ];
__device__ __align__(16) __nv_bfloat16 g_Al[(size_t)MSZ * KSZ];
__device__ __align__(16) __nv_bfloat16 g_Bb[(size_t)NSZ * KSZ];
__device__ double g_abs_sum;
__device__ float  g_inv_scale;

// ---------------- PTX helpers (all non-'a' features: valid for compute_103) ----------------
__device__ __forceinline__ uint32_t s2u(const void* p) {
    return (uint32_t)__cvta_generic_to_shared(p);
}
__device__ __forceinline__ uint32_t swz(uint32_t off) { return off ^ ((off >> 3) & 0x70); }

__device__ __forceinline__ void cp16(uint32_t dst, const void* src) {
    asm volatile("cp.async.cg.shared.global [%0], [%1], 16;" :: "r"(dst), "l"(src));
}
__device__ __forceinline__ void cp_commit() { asm volatile("cp.async.commit_group;" ::: "memory"); }
__device__ __forceinline__ void cp_wait1()  { asm volatile("cp.async.wait_group 1;" ::: "memory"); }

__device__ __forceinline__ void ldsm_x4(uint32_t& r0, uint32_t& r1, uint32_t& r2, uint32_t& r3,
                                        uint32_t addr) {
    asm volatile("ldmatrix.sync.aligned.m8n8.x4.shared.b16 {%0,%1,%2,%3}, [%4];"
                 : "=r"(r0), "=r"(r1), "=r"(r2), "=r"(r3) : "r"(addr));
}

__device__ __forceinline__ void mma_bf16(float* d, const uint32_t* a, const uint32_t* b) {
    asm volatile(
        "mma.sync.aligned.m16n8k16.row.col.f32.bf16.bf16.f32 "
        "{%0,%1,%2,%3}, {%4,%5,%6,%7}, {%8,%9}, {%0,%1,%2,%3};"
        : "+f"(d[0]), "+f"(d[1]), "+f"(d[2]), "+f"(d[3])
        : "r"(a[0]), "r"(a[1]), "r"(a[2]), "r"(a[3]), "r"(b[0]), "r"(b[1]));
}

// ---------------- pre-pass: 3-way bf16 split of A = x*inS*wS ----------------
__global__ void split_kernel(const float4* __restrict__ x,
                             const float* __restrict__ inS,
                             const float* __restrict__ wS, int n4) {
    int i = blockIdx.x * blockDim.x + threadIdx.x;
    if (i >= n4) return;
    const float s1 = inS[0], s2 = wS[0];
    float4 v = x[i];
    float t[4] = {v.x, v.y, v.z, v.w};
    __nv_bfloat16 h[4], m[4], l[4];
    #pragma unroll
    for (int j = 0; j < 4; j++) {
        float tv = __fmul_rn(__fmul_rn(t[j], s1), s2);   // reference rounding order
        h[j] = __float2bfloat16_rn(tv);
        float r1 = tv - __bfloat162float(h[j]);          // exact
        m[j] = __float2bfloat16_rn(r1);
        float r2 = r1 - __bfloat162float(m[j]);          // exact
        l[j] = __float2bfloat16_rn(r2);                  // exact: hi+mid+lo == tv
    }
    *(uint2*)&g_Ah[(size_t)i * 4] = *(uint2*)h;
    *(uint2*)&g_Am[(size_t)i * 4] = *(uint2*)m;
    *(uint2*)&g_Al[(size_t)i * 4] = *(uint2*)l;
}

__global__ void wconv_kernel(const float4* __restrict__ w, int n4) {
    int i = blockIdx.x * blockDim.x + threadIdx.x;
    if (i >= n4) return;
    float4 v = w[i];
    __nv_bfloat16 b[4] = {__float2bfloat16_rn(v.x), __float2bfloat16_rn(v.y),
                          __float2bfloat16_rn(v.z), __float2bfloat16_rn(v.w)};  // ternary: exact
    *(uint2*)&g_Bb[(size_t)i * 4] = *(uint2*)b;
}

__global__ void reset_kernel() { g_abs_sum = 0.0; }

// ---------------- HMMA GEMM: C[M,N] = (Ah+Am+Al)[M,K] @ Bb[N,K]^T ----------------
__global__ __launch_bounds__(THREADS, 1)
void gemm_kernel(float* __restrict__ C) {
    extern __shared__ char smem[];
    const uint32_t sb = s2u(smem);

    const int tid = threadIdx.x, wid = tid >> 5, lane = tid & 31;
    const int wm = wid & 1;          // 2 warps in m -> 64 rows each
    const int wn = wid >> 1;         // 4 warps in n -> 32 cols each
    const int m0 = blockIdx.y * BM;
    const int n0 = blockIdx.x * BN;

    // acc: RZ-chained mma accumulator (flushed each k-tile)
    // carry: RN fp32 running sum (breaks the tensor-core RZ bias chain)
    float acc[4][4][4], carry[4][4][4];
    #pragma unroll
    for (int i = 0; i < 4; i++)
        #pragma unroll
        for (int j = 0; j < 4; j++)
            #pragma unroll
            for (int r = 0; r < 4; r++) { acc[i][j][r] = 0.f; carry[i][j][r] = 0.f; }

    // --- cp.async stage loader: 4 planes x 128 rows x 128B, SW128 swizzled ---
    auto load_stage = [&](int kt) {
        const uint32_t stb = sb + (uint32_t)(kt & 1) * STAGE_BYTES;
        const int kb = kt * BK;
        #pragma unroll
        for (int p = 0; p < 4; p++) {
            const __nv_bfloat16* base =
                (p == 0 ? g_Ah : p == 1 ? g_Am : p == 2 ? g_Al : g_Bb) +
                (size_t)(p == 3 ? n0 : m0) * KSZ + kb;
            #pragma unroll
            for (int j = 0; j < 4; j++) {
                int q = tid + THREADS * j;          // 0..1023
                int row = q >> 3, c = q & 7;
                cp16(stb + p * PLANE_BYTES + swz(row * 128 + c * 16),
                     base + (size_t)row * KSZ + c * 8);
            }
        }
    };

    // --- per-lane ldmatrix row/byte components (before swizzle) ---
    const int a_row  = wm * 64 + (lane & 15);                       // + mt*16
    const int a_koff = (lane >> 4) * 16;                            // + ks*32
    const int b_row  = wn * 32 + ((lane >> 4) << 3) + (lane & 7);   // + pair*16
    const int b_koff = ((lane >> 3) & 1) * 16;                      // + ks*32

    load_stage(0);
    cp_commit();

    for (int kt = 0; kt < KTILES; kt++) {
        if (kt + 1 < KTILES) load_stage(kt + 1);
        cp_commit();            // uniform group count (empty group in tail)
        cp_wait1();             // stage kt resident
        __syncthreads();

        const uint32_t stb = sb + (uint32_t)(kt & 1) * STAGE_BYTES;
        #pragma unroll
        for (int ks = 0; ks < 4; ks++) {
            // B fragments for all 4 n-tiles (shared by the 3 A planes)
            uint32_t bfr[2][4];
            #pragma unroll
            for (int pair = 0; pair < 2; pair++) {
                uint32_t off = (uint32_t)(b_row + pair * 16) * 128 + ks * 32 + b_koff;
                ldsm_x4(bfr[pair][0], bfr[pair][1], bfr[pair][2], bfr[pair][3],
                        stb + 3 * PLANE_BYTES + swz(off));
            }
            #pragma unroll
            for (int p = 0; p < 3; p++) {
                #pragma unroll
                for (int mt = 0; mt < 4; mt++) {
                    uint32_t afr[4];
                    uint32_t off = (uint32_t)(a_row + mt * 16) * 128 + ks * 32 + a_koff;
                    ldsm_x4(afr[0], afr[1], afr[2], afr[3],
                            stb + p * PLANE_BYTES + swz(off));
                    #pragma unroll
                    for (int nt = 0; nt < 4; nt++)
                        mma_bf16(acc[mt][nt], afr, &bfr[nt >> 1][(nt & 1) * 2]);
                }
            }
        }

        // flush: RN add tile partial into carry, reset mma accumulator.
        // Cuts the tensor-core RZ accumulation chain from 384 to 12 steps.
        #pragma unroll
        for (int i = 0; i < 4; i++)
            #pragma unroll
            for (int j = 0; j < 4; j++)
                #pragma unroll
                for (int r = 0; r < 4; r++) {
                    carry[i][j][r] = __fadd_rn(carry[i][j][r], acc[i][j][r]);
                    acc[i][j][r] = 0.f;
                }

        __syncthreads();        // protect buffer (kt) before reload at kt+2
    }

    // ---------------- epilogue: store C + fused abs-sum ----------------
    float asum = 0.f;
    {
        const int rbase = m0 + wm * 64 + (lane >> 2);
        const int cbase = n0 + wn * 32 + (lane & 3) * 2;
        #pragma unroll
        for (int mt = 0; mt < 4; mt++) {
            #pragma unroll
            for (int nt = 0; nt < 4; nt++) {
                float v0 = carry[mt][nt][0], v1 = carry[mt][nt][1];
                float v2 = carry[mt][nt][2], v3 = carry[mt][nt][3];
                float* p0 = C + (size_t)(rbase + mt * 16) * NSZ + cbase + nt * 8;
                float* p1 = p0 + 8 * NSZ;
                *(float2*)p0 = make_float2(v0, v1);
                *(float2*)p1 = make_float2(v2, v3);
                asum += fabsf(v0) + fabsf(v1) + fabsf(v2) + fabsf(v3);
            }
        }
    }

    __shared__ float red[THREADS / 32];
    #pragma unroll
    for (int off = 16; off > 0; off >>= 1)
        asum += __shfl_down_sync(0xffffffffu, asum, off);
    if (lane == 0) red[wid] = asum;
    __syncthreads();
    if (wid == 0) {
        float v = (lane < THREADS / 32) ? red[lane] : 0.f;
        #pragma unroll
        for (int off = 4; off > 0; off >>= 1)
            v += __shfl_down_sync(0xffffffffu, v, off);
        if (lane == 0) atomicAdd(&g_abs_sum, (double)v);
    }
}

// ---------------- finalize + quantize ----------------
__global__ void finalize_kernel(float* __restrict__ scale_slot, size_t mn) {
    double mean = g_abs_sum / (double)mn;
    float scale = (float)mean;
    if (scale < 1e-5f) scale = 1e-5f;
    *scale_slot = scale;
    g_inv_scale = (float)(1.0 / (double)scale);
}

__global__ void quantize_kernel(float4* __restrict__ C, int n4) {
    int i = blockIdx.x * blockDim.x + threadIdx.x;
    if (i >= n4) return;
    const float inv = g_inv_scale;
    float4 v = C[i];
    v.x = fminf(fmaxf(rintf(v.x * inv), -1.f), 1.f);
    v.y = fminf(fmaxf(rintf(v.y * inv), -1.f), 1.f);
    v.z = fminf(fmaxf(rintf(v.z * inv), -1.f), 1.f);
    v.w = fminf(fmaxf(rintf(v.w * inv), -1.f), 1.f);
    C[i] = v;
}

extern "C" void kernel_launch(void* const* d_in, const int* in_sizes, int n_in,
                              void* d_out, int out_size)
{
    const float* x   = (const float*)d_in[0];
    const float* inS = (const float*)d_in[1];
    const float* qw  = (const float*)d_in[2];
    const float* wS  = (const float*)d_in[3];
    float* out = (float*)d_out;
    const size_t mn = (size_t)MSZ * NSZ;

    cudaFuncSetAttribute(gemm_kernel, cudaFuncAttributeMaxDynamicSharedMemorySize, SMEM_BYTES);

    const int a4 = MSZ * KSZ / 4;
    split_kernel<<<(a4 + 255) / 256, 256>>>((const float4*)x, inS, wS, a4);
    const int w4 = NSZ * KSZ / 4;
    wconv_kernel<<<(w4 + 255) / 256, 256>>>((const float4*)qw, w4);
    reset_kernel<<<1, 1>>>();

    dim3 grid(NSZ / BN, MSZ / BM);   // (16, 128) — x-major keeps A row-blocks hot in L2
    gemm_kernel<<<grid, THREADS, SMEM_BYTES>>>(out);

    finalize_kernel<<<1, 1>>>(out + mn, mn);

    const int n4 = (int)(mn / 4);
    quantize_kernel<<<(n4 + 255) / 256, 256>>>((float4*)out, n4);
}